// round 10
// baseline (speedup 1.0000x reference)
#include <cuda_runtime.h>
#include <cuda_bf16.h>
#include <cstdint>

// LSTM B=65536, T=7, H=128, fused recurrence via warp-level mma.sync (bf16->f32).
// CTA = 512 thr / 16 warps / 64 rows, TWO independent 8-warp groups (named bars).
// R10 = R9 (A regs once + np-serial MMA/epilogue interleave) + epilogue L1 diet:
//   bias/W_ih LDS shared across mi (32->16 LDS.128/thr/step),
//   W_out hoisted to 8 regs, h stores packed bf16x2 via shfl (16->8 STS),
//   pred reduce/output deferred to after the T loop.

#define T 7
#define MTILE 64
#define NTH 512
#define WSTR 136   // bf16 elems per W' row (17x16B pitch -> conflict-free ldmatrix)
#define HSTR 136

#define W_OFF   0u
#define H0_OFF  139264u               // 512*136*2
#define H1_OFF  156672u
#define F32_OFF 174080u
#define F_BIAS 0                      // 512 (permuted j = u*4+g)
#define F_WIH  512                    // 512
#define F_XS   1024                   // 64 rows x 8 slots
#define F_PRED 1536                   // 7 steps x 64 rows x 8 warps
#define F_COUNT (1536 + 7 * 512)
#define SMEM_TOTAL (174080 + F_COUNT * 4)   // 194560

static __device__ __forceinline__ uint32_t smem_u32(const void* p) {
    uint32_t a;
    asm("{ .reg .u64 t; cvta.to.shared.u64 t, %1; cvt.u32.u64 %0, t; }"
        : "=r"(a) : "l"(p));
    return a;
}
static __device__ __forceinline__ float tanh_fast(float v) {
    float y; asm("tanh.approx.f32 %0, %1;" : "=f"(y) : "f"(v)); return y;
}
static __device__ __forceinline__ float sigmoid_fast(float v) {
    return 0.5f * tanh_fast(0.5f * v) + 0.5f;
}
static __device__ __forceinline__ uint32_t pack_bf16x2(float lo, float hi) {
    uint32_t r;
    asm("cvt.rn.bf16x2.f32 %0, %1, %2;" : "=r"(r) : "f"(hi), "f"(lo));
    return r;
}

#define LDSM_X4(r0, r1, r2, r3, addr) \
    asm volatile("ldmatrix.sync.aligned.m8n8.x4.shared.b16 {%0,%1,%2,%3}, [%4];" \
        : "=r"(r0), "=r"(r1), "=r"(r2), "=r"(r3) : "r"(addr))

#define MMA16816(D, A, B0, B1) \
    asm volatile("mma.sync.aligned.m16n8k16.row.col.f32.bf16.bf16.f32 " \
        "{%0,%1,%2,%3}, {%4,%5,%6,%7}, {%8,%9}, {%0,%1,%2,%3};" \
        : "+f"((D)[0]), "+f"((D)[1]), "+f"((D)[2]), "+f"((D)[3]) \
        : "r"((A)[0]), "r"((A)[1]), "r"((A)[2]), "r"((A)[3]), "r"(B0), "r"(B1))

__global__ __launch_bounds__(NTH, 1)
void lstm_mma_kernel(const float* __restrict__ x,
                     const float* __restrict__ x0,
                     const float* __restrict__ W_ih,
                     const float* __restrict__ W_hh,
                     const float* __restrict__ b_ih,
                     const float* __restrict__ b_hh,
                     const float* __restrict__ W_out,
                     const float* __restrict__ b_out,
                     float* __restrict__ out)
{
    extern __shared__ char smem[];
    const uint32_t sb = smem_u32(smem);
    float* f32s = (float*)(smem + F32_OFF);

    const int tid  = threadIdx.x;
    const int wid  = tid >> 5;
    const int grp  = wid >> 3;        // independent 32-row group
    const int gwid = wid & 7;         // col-warp: units gwid*16..+15
    const int lane = tid & 31;
    const int q    = lane & 3;
    const int par  = q & 1;
    const int hu   = q >> 1;
    const int rowBase = blockIdx.x * MTILE;

    // ---- one-time staging (full CTA) ----
#pragma unroll
    for (int it = 0; it < 32; it++) {
        int idx = tid + it * NTH;
        int j   = idx >> 5;
        int kq  = (idx & 31) * 4;
        int src = (j & 3) * 128 + (j >> 2);
        float4 w4 = *(const float4*)(W_hh + src * 128 + kq);
        uint32_t o = (uint32_t)(j * WSTR + kq) * 2;
        *(uint32_t*)(smem + o)     = pack_bf16x2(w4.x, w4.y);
        *(uint32_t*)(smem + o + 4) = pack_bf16x2(w4.z, w4.w);
    }
    for (int i = tid; i < (int)(64 * HSTR * 2 / 4); i += NTH)
        *(uint32_t*)(smem + H0_OFF + i * 4) = 0u;
    for (int j = tid; j < 512; j += NTH) {
        int u = j >> 2, g = j & 3, src = g * 128 + u;
        f32s[F_BIAS + j] = b_ih[src] + b_hh[src];
        f32s[F_WIH + j]  = W_ih[src];
    }
    {   // 64 rows x 8 step slots
        int row = tid >> 3, sl = tid & 7;
        f32s[F_XS + tid] = (sl == 0) ? x0[rowBase + row]
                                     : x[(rowBase + row) * T + (sl > 6 ? 6 : sl - 1)];
    }

    // W_out -> registers (loop-invariant per thread)
    float wout[8];
#pragma unroll
    for (int nt = 0; nt < 8; nt++) wout[nt] = W_out[gwid * 16 + nt * 2 + hu];

    __syncthreads();   // last CTA-wide barrier; groups free-run from here

    float cst[2][8];
#pragma unroll
    for (int mi = 0; mi < 2; mi++)
#pragma unroll
        for (int nt = 0; nt < 8; nt++) cst[mi][nt] = 0.0f;

    const uint32_t aOff = (uint32_t)(((lane & 15) * HSTR + ((lane >> 4) & 1) * 8) * 2);
    const uint32_t bOff = (uint32_t)(((gwid * 64 + ((lane >> 4) & 1) * 8 + (lane & 7)) * WSTR
                                      + ((lane >> 3) & 1) * 8) * 2);
    const int rowIn = (lane >> 2) + par * 8;
    const int gtid  = tid & 255;
    const int barid = grp + 1;

    for (int s = 0; s < T; s++) {
        const uint32_t hcur = (s & 1) ? H1_OFF : H0_OFF;
        const uint32_t hnxt = (s & 1) ? H0_OFF : H1_OFF;

        const float xv[2] = { f32s[F_XS + (grp * 32 + rowIn) * 8 + s],
                              f32s[F_XS + (grp * 32 + 16 + rowIn) * 8 + s] };
        float pred[2] = {0.0f, 0.0f};

        // ---- load ALL A (h) fragments once: 64 regs, 16 ldsm ----
        uint32_t A[2][8][4];
#pragma unroll
        for (int kc = 0; kc < 8; kc++)
#pragma unroll
            for (int mi = 0; mi < 2; mi++)
                LDSM_X4(A[mi][kc][0], A[mi][kc][1], A[mi][kc][2], A[mi][kc][3],
                        sb + hcur + aOff +
                        (uint32_t)(((grp * 32 + mi * 16) * HSTR + kc * 16) * 2));

        // ---- 4 serial np-slices: MMA burst + immediate epilogue ----
#pragma unroll
        for (int np = 0; np < 4; np++) {
            float acc[2][2][4];
#pragma unroll
            for (int mi = 0; mi < 2; mi++)
#pragma unroll
                for (int t = 0; t < 2; t++)
#pragma unroll
                    for (int e = 0; e < 4; e++) acc[mi][t][e] = 0.0f;

#pragma unroll
            for (int kc = 0; kc < 8; kc++) {
                uint32_t b0, b1, b2, b3;
                LDSM_X4(b0, b1, b2, b3,
                        sb + W_OFF + bOff + (uint32_t)((np * 16 * WSTR + kc * 16) * 2));
#pragma unroll
                for (int mi = 0; mi < 2; mi++) {
                    MMA16816(acc[mi][0], A[mi][kc], b0, b1);
                    MMA16816(acc[mi][1], A[mi][kc], b2, b3);
                }
            }

            // epilogue: cells nt = np*2 + t; bias/W_ih shared across mi
#pragma unroll
            for (int t = 0; t < 2; t++) {
                const int nt = np * 2 + t;
                const int u  = gwid * 16 + nt * 2 + hu;
                const float4 b4 = *(const float4*)&f32s[F_BIAS + u * 4];
                const float4 w4 = *(const float4*)&f32s[F_WIH + u * 4];
#pragma unroll
                for (int mi = 0; mi < 2; mi++) {
                    float s0 = par ? acc[mi][t][0] : acc[mi][t][2];
                    float s1 = par ? acc[mi][t][1] : acc[mi][t][3];
                    float r0 = __shfl_xor_sync(0xffffffffu, s0, 1);
                    float r1 = __shfl_xor_sync(0xffffffffu, s1, 1);
                    float gi = par ? r0 : acc[mi][t][0];
                    float gf = par ? r1 : acc[mi][t][1];
                    float gg = par ? acc[mi][t][2] : r0;
                    float go = par ? acc[mi][t][3] : r1;

                    gi += b4.x + xv[mi] * w4.x;
                    gf += b4.y + xv[mi] * w4.y;
                    gg += b4.z + xv[mi] * w4.z;
                    go += b4.w + xv[mi] * w4.w;

                    float ig = sigmoid_fast(gi);
                    float fg = sigmoid_fast(gf);
                    float g_ = tanh_fast(gg);
                    float og = sigmoid_fast(go);
                    float cn = fg * cst[mi][nt] + ig * g_;
                    cst[mi][nt] = cn;
                    float hn = og * tanh_fast(cn);
                    pred[mi] += hn * wout[nt];

                    // packed h store: hu==0 lane writes (u, u+1) as bf16x2
                    float hx = __shfl_xor_sync(0xffffffffu, hn, 2);
                    if (hu == 0) {
                        const int row_eff = grp * 32 + mi * 16 + rowIn;
                        *(uint32_t*)(smem + hnxt +
                            (uint32_t)((row_eff * HSTR + gwid * 16 + nt * 2) * 2)) =
                            pack_bf16x2(hn, hx);
                    }
                }
            }
        }

        // pred partials -> deferred SMEM array (reduced after the loop)
#pragma unroll
        for (int mi = 0; mi < 2; mi++) {
            pred[mi] += __shfl_xor_sync(0xffffffffu, pred[mi], 2);
            if (q < 2)
                f32s[F_PRED + s * 512 + (grp * 32 + mi * 16 + rowIn) * 8 + gwid] = pred[mi];
        }

        // group-private barrier: h(next) visible to own group
        asm volatile("bar.sync %0, %1;" :: "r"(barid), "r"(256) : "memory");
    }

    // ---- deferred output: 32 rows x 7 steps per group ----
    const float bout = b_out[0];
    for (int idx = gtid; idx < 32 * T; idx += 256) {
        const int row = grp * 32 + idx / T;
        const int s   = idx % T;
        float p = bout;
        const float* pp = &f32s[F_PRED + s * 512 + row * 8];
#pragma unroll
        for (int w = 0; w < 8; w++) p += pp[w];
        out[(rowBase + row) * T + s] = p;
    }
}

extern "C" void kernel_launch(void* const* d_in, const int* in_sizes, int n_in,
                              void* d_out, int out_size)
{
    const float* x     = (const float*)d_in[0];
    const float* x0    = (const float*)d_in[1];
    const float* W_ih  = (const float*)d_in[2];
    const float* W_hh  = (const float*)d_in[3];
    const float* b_ih  = (const float*)d_in[4];
    const float* b_hh  = (const float*)d_in[5];
    const float* W_out = (const float*)d_in[6];
    const float* b_out = (const float*)d_in[7];
    float* out = (float*)d_out;

    const int B = in_sizes[1];

    cudaFuncSetAttribute(lstm_mma_kernel,
                         cudaFuncAttributeMaxDynamicSharedMemorySize, SMEM_TOTAL);

    lstm_mma_kernel<<<B / MTILE, NTH, SMEM_TOTAL>>>(
        x, x0, W_ih, W_hh, b_ih, b_hh, W_out, b_out, out);
}

// round 11
// speedup vs baseline: 1.1412x; 1.1412x over previous
#include <cuda_runtime.h>
#include <cuda_bf16.h>
#include <cstdint>

// LSTM B=65536, T=7, H=128, fused recurrence via warp-level mma.sync (bf16->f32).
// CTA = 512 thr / 16 warps / 64 rows, TWO independent 8-warp groups (named bars).
// R11 = R8 structure + SHFL-FREE gate regroup: W' columns permuted so each
// thread's C-fragment holds all 4 gates of one unit in-register:
//   W' col c = nt*8+p (within warp slice)  <-  gate=(p&1)+2*(nt&1),
//   unit = gw*16 + (nt>>1)*4 + (p>>1)
// Thread q (cols 2q,2q+1) of tile pair (2pr, 2pr+1) owns unit gw*16+pr*4+q:
//   even tile elems = (i,f), odd tile elems = (g,o), rows lane>>2 and +8.

#define T 7
#define MTILE 64
#define NTH 512
#define WSTR 136   // bf16 elems per W' row (17x16B pitch -> conflict-free ldmatrix)
#define HSTR 136

#define W_OFF   0u
#define H0_OFF  139264u               // 512*136*2
#define H1_OFF  156672u
#define F32_OFF 174080u
#define F_BIAS 0                      // 512, layout u*4+g
#define F_WIH  512                    // 512, layout u*4+g
#define F_XS   1024                   // 64 rows x 8 slots
#define F_PRED 1536                   // 2 x (64 rows x 8 col-warps)
#define F_COUNT 2560
#define SMEM_TOTAL (174080 + F_COUNT * 4)

static __device__ __forceinline__ uint32_t smem_u32(const void* p) {
    uint32_t a;
    asm("{ .reg .u64 t; cvta.to.shared.u64 t, %1; cvt.u32.u64 %0, t; }"
        : "=r"(a) : "l"(p));
    return a;
}
static __device__ __forceinline__ float tanh_fast(float v) {
    float y; asm("tanh.approx.f32 %0, %1;" : "=f"(y) : "f"(v)); return y;
}
static __device__ __forceinline__ float sigmoid_fast(float v) {
    return 0.5f * tanh_fast(0.5f * v) + 0.5f;
}
static __device__ __forceinline__ uint32_t pack_bf16x2(float lo, float hi) {
    uint32_t r;
    asm("cvt.rn.bf16x2.f32 %0, %1, %2;" : "=r"(r) : "f"(hi), "f"(lo));
    return r;
}

#define LDSM_X4(r0, r1, r2, r3, addr) \
    asm volatile("ldmatrix.sync.aligned.m8n8.x4.shared.b16 {%0,%1,%2,%3}, [%4];" \
        : "=r"(r0), "=r"(r1), "=r"(r2), "=r"(r3) : "r"(addr))

#define MMA16816(D, A, B0, B1) \
    asm volatile("mma.sync.aligned.m16n8k16.row.col.f32.bf16.bf16.f32 " \
        "{%0,%1,%2,%3}, {%4,%5,%6,%7}, {%8,%9}, {%0,%1,%2,%3};" \
        : "+f"((D)[0]), "+f"((D)[1]), "+f"((D)[2]), "+f"((D)[3]) \
        : "r"((A)[0]), "r"((A)[1]), "r"((A)[2]), "r"((A)[3]), "r"(B0), "r"(B1))

__global__ __launch_bounds__(NTH, 1)
void lstm_mma_kernel(const float* __restrict__ x,
                     const float* __restrict__ x0,
                     const float* __restrict__ W_ih,
                     const float* __restrict__ W_hh,
                     const float* __restrict__ b_ih,
                     const float* __restrict__ b_hh,
                     const float* __restrict__ W_out,
                     const float* __restrict__ b_out,
                     float* __restrict__ out)
{
    extern __shared__ char smem[];
    const uint32_t sb = smem_u32(smem);
    float* f32s = (float*)(smem + F32_OFF);

    const int tid  = threadIdx.x;
    const int wid  = tid >> 5;
    const int grp  = wid >> 3;        // independent 32-row group
    const int gwid = wid & 7;         // col-warp: units gwid*16..+15
    const int lane = tid & 31;
    const int q    = lane & 3;
    const int rq   = lane >> 2;       // row 0..7 within 16-row tile (+8 pair)
    const int rowBase = blockIdx.x * MTILE;

    // ---- one-time staging (full CTA) ----
    // W' row j: gw=j>>6, c=j&63, nt=c>>3, p=c&7
    //   gate=(p&1)+2*(nt&1); unit=(gw<<4)+((nt>>1)<<2)+(p>>1); src=gate*128+unit
#pragma unroll
    for (int it = 0; it < 32; it++) {
        int idx = tid + it * NTH;
        int j   = idx >> 5;
        int kq  = (idx & 31) * 4;
        int c   = j & 63, nt = c >> 3, p = c & 7;
        int gate = (p & 1) + ((nt & 1) << 1);
        int unit = ((j >> 6) << 4) + ((nt >> 1) << 2) + (p >> 1);
        int src  = gate * 128 + unit;
        float4 w4 = *(const float4*)(W_hh + src * 128 + kq);
        uint32_t o = (uint32_t)(j * WSTR + kq) * 2;
        *(uint32_t*)(smem + o)     = pack_bf16x2(w4.x, w4.y);
        *(uint32_t*)(smem + o + 4) = pack_bf16x2(w4.z, w4.w);
    }
    for (int i = tid; i < (int)(64 * HSTR * 2 / 4); i += NTH)
        *(uint32_t*)(smem + H0_OFF + i * 4) = 0u;
    for (int j = tid; j < 512; j += NTH) {          // bias/W_ih, layout u*4+g
        int u = j >> 2, g = j & 3, src = g * 128 + u;
        f32s[F_BIAS + j] = b_ih[src] + b_hh[src];
        f32s[F_WIH + j]  = W_ih[src];
    }
    {   // 64 rows x 8 step slots
        int row = tid >> 3, sl = tid & 7;
        f32s[F_XS + tid] = (sl == 0) ? x0[rowBase + row]
                                     : x[(rowBase + row) * T + (sl > 6 ? 6 : sl - 1)];
    }

    // W_out for this thread's 4 units (one per pair)
    float wout[4];
#pragma unroll
    for (int pr = 0; pr < 4; pr++) wout[pr] = W_out[gwid * 16 + pr * 4 + q];

    __syncthreads();   // last CTA-wide barrier; groups free-run from here

    float cst[2][4][2];   // [mi][pair][row half]
#pragma unroll
    for (int mi = 0; mi < 2; mi++)
#pragma unroll
        for (int pr = 0; pr < 4; pr++)
            cst[mi][pr][0] = cst[mi][pr][1] = 0.0f;

    const uint32_t aOff = (uint32_t)(((lane & 15) * HSTR + ((lane >> 4) & 1) * 8) * 2);
    const uint32_t bOff = (uint32_t)(((gwid * 64 + ((lane >> 4) & 1) * 8 + (lane & 7)) * WSTR
                                      + ((lane >> 3) & 1) * 8) * 2);
    const int gtid  = tid & 255;
    const int barid = grp + 1;

    for (int s = 0; s < T; s++) {
        const uint32_t hcur = (s & 1) ? H1_OFF : H0_OFF;
        const uint32_t hnxt = (s & 1) ? H0_OFF : H1_OFF;

        float xv[2][2];
#pragma unroll
        for (int mi = 0; mi < 2; mi++)
#pragma unroll
            for (int r = 0; r < 2; r++)
                xv[mi][r] = f32s[F_XS + (grp * 32 + mi * 16 + rq + r * 8) * 8 + s];
        float pred[2][2] = {{0.0f, 0.0f}, {0.0f, 0.0f}};

        float acc[2][8][4];
#pragma unroll
        for (int mi = 0; mi < 2; mi++)
#pragma unroll
            for (int nt = 0; nt < 8; nt++)
#pragma unroll
                for (int e = 0; e < 4; e++) acc[mi][nt][e] = 0.0f;

        // shfl-free epilogue for pair pr of tile mi: all gates in-register
        auto epi_pair = [&](int mi, int pr) {
            const int u = gwid * 16 + pr * 4 + q;
            const float4 b4 = *(const float4*)&f32s[F_BIAS + u * 4];
            const float4 w4 = *(const float4*)&f32s[F_WIH + u * 4];
            const float* aif = acc[mi][pr * 2];        // (i,f) rows r0, r0+8
            const float* ago = acc[mi][pr * 2 + 1];    // (g,o)
#pragma unroll
            for (int r = 0; r < 2; r++) {
                float gi = aif[r * 2 + 0] + b4.x + xv[mi][r] * w4.x;
                float gf = aif[r * 2 + 1] + b4.y + xv[mi][r] * w4.y;
                float gg = ago[r * 2 + 0] + b4.z + xv[mi][r] * w4.z;
                float go = ago[r * 2 + 1] + b4.w + xv[mi][r] * w4.w;
                float ig = sigmoid_fast(gi);
                float fg = sigmoid_fast(gf);
                float g_ = tanh_fast(gg);
                float og = sigmoid_fast(go);
                float cn = fg * cst[mi][pr][r] + ig * g_;
                cst[mi][pr][r] = cn;
                float hn = og * tanh_fast(cn);
                pred[mi][r] += hn * wout[pr];
                const int row_eff = grp * 32 + mi * 16 + rq + r * 8;
                *(__nv_bfloat16*)(smem + hnxt +
                    (uint32_t)((row_eff * HSTR + u) * 2)) = __float2bfloat16(hn);
            }
        };

        // ---- PASS 1: np 0..1 -> pairs 0,1 complete ----
#pragma unroll
        for (int kc = 0; kc < 8; kc++) {
            uint32_t a[2][4];
#pragma unroll
            for (int mi = 0; mi < 2; mi++)
                LDSM_X4(a[mi][0], a[mi][1], a[mi][2], a[mi][3],
                        sb + hcur + aOff +
                        (uint32_t)(((grp * 32 + mi * 16) * HSTR + kc * 16) * 2));
#pragma unroll
            for (int np = 0; np < 2; np++) {
                uint32_t b0, b1, b2, b3;
                LDSM_X4(b0, b1, b2, b3,
                        sb + W_OFF + bOff + (uint32_t)((np * 16 * WSTR + kc * 16) * 2));
#pragma unroll
                for (int mi = 0; mi < 2; mi++) {
                    MMA16816(acc[mi][np * 2],     a[mi], b0, b1);
                    MMA16816(acc[mi][np * 2 + 1], a[mi], b2, b3);
                }
            }
        }

        // ---- FUSED PASS 2 (np 2..3) + epilogues of pairs 0,1 ----
#pragma unroll
        for (int kc = 0; kc < 8; kc++) {
            uint32_t a[2][4];
#pragma unroll
            for (int mi = 0; mi < 2; mi++)
                LDSM_X4(a[mi][0], a[mi][1], a[mi][2], a[mi][3],
                        sb + hcur + aOff +
                        (uint32_t)(((grp * 32 + mi * 16) * HSTR + kc * 16) * 2));
#pragma unroll
            for (int np = 2; np < 4; np++) {
                uint32_t b0, b1, b2, b3;
                LDSM_X4(b0, b1, b2, b3,
                        sb + W_OFF + bOff + (uint32_t)((np * 16 * WSTR + kc * 16) * 2));
#pragma unroll
                for (int mi = 0; mi < 2; mi++) {
                    MMA16816(acc[mi][np * 2],     a[mi], b0, b1);
                    MMA16816(acc[mi][np * 2 + 1], a[mi], b2, b3);
                }
            }
            if (kc & 1)
                epi_pair((kc >> 1) & 1, kc >> 2);   // (0,0),(1,0),(0,1),(1,1)
        }

        // ---- trailing epilogues: pairs 2,3 ----
        epi_pair(0, 2); epi_pair(1, 2); epi_pair(0, 3); epi_pair(1, 3);

        // ---- pred partials (only 8 shfls/step) ----
        const int pb = F_PRED + (s & 1) * 512;
#pragma unroll
        for (int mi = 0; mi < 2; mi++)
#pragma unroll
            for (int r = 0; r < 2; r++) {
                float pv = pred[mi][r];
                pv += __shfl_xor_sync(0xffffffffu, pv, 1);
                pv += __shfl_xor_sync(0xffffffffu, pv, 2);
                if (q == 0)
                    f32s[pb + (grp * 32 + mi * 16 + rq + r * 8) * 8 + gwid] = pv;
            }

        asm volatile("bar.sync %0, %1;" :: "r"(barid), "r"(256) : "memory");

        if (gtid < 32) {
            const int row = grp * 32 + gtid;
            float p = b_out[0];
            const float* pp = &f32s[pb + row * 8];
#pragma unroll
            for (int w = 0; w < 8; w++) p += pp[w];
            out[(rowBase + row) * T + s] = p;
        }
    }
}

extern "C" void kernel_launch(void* const* d_in, const int* in_sizes, int n_in,
                              void* d_out, int out_size)
{
    const float* x     = (const float*)d_in[0];
    const float* x0    = (const float*)d_in[1];
    const float* W_ih  = (const float*)d_in[2];
    const float* W_hh  = (const float*)d_in[3];
    const float* b_ih  = (const float*)d_in[4];
    const float* b_hh  = (const float*)d_in[5];
    const float* W_out = (const float*)d_in[6];
    const float* b_out = (const float*)d_in[7];
    float* out = (float*)d_out;

    const int B = in_sizes[1];

    cudaFuncSetAttribute(lstm_mma_kernel,
                         cudaFuncAttributeMaxDynamicSharedMemorySize, SMEM_TOTAL);

    lstm_mma_kernel<<<B / MTILE, NTH, SMEM_TOTAL>>>(
        x, x0, W_ih, W_hh, b_ih, b_hh, W_out, b_out, out);
}